// round 1
// baseline (speedup 1.0000x reference)
#include <cuda_runtime.h>
#include <math.h>
#include <stddef.h>

#define B_  16384
#define D_  768
#define H_  768
#define G4_ 3072   // 4*H
#define E_  4
#define L_  2
#define T_  10

// ---------------- scratch (static device globals; no allocation) ----------------
__device__ float g_xWi [(size_t)B_ * G4_];
__device__ float g_gates[(size_t)B_ * G4_];
__device__ float g_h   [(size_t)B_ * H_];
__device__ float g_c   [(size_t)B_ * H_];
__device__ float g_hsum[(size_t)B_ * H_];
__device__ float g_x0  [(size_t)B_ * H_];
__device__ float g_hmid[(size_t)B_ * H_];
__device__ float g_accA[(size_t)B_ * D_];
__device__ float g_accB[(size_t)B_ * D_];
__device__ float g_hp  [B_];
__device__ float g_rem [B_];
__device__ float g_w   [B_ * E_];

__device__ __forceinline__ float sigf(float x) { return 1.f / (1.f + expf(-x)); }

// ---------------- utility ----------------
__global__ void fill0(float* p, size_t n) {
    size_t i  = (size_t)blockIdx.x * blockDim.x + threadIdx.x;
    size_t st = (size_t)gridDim.x * blockDim.x;
    for (; i < n; i += st) p[i] = 0.f;
}

// ---------------- SGEMM: C[M,N] = A[M,K] @ W[N,K]^T  (+ epilogue) ----------------
// All of M, N divisible by 128; K divisible by 8. No bounds checks.
// MODE 0: C = AB^T + bias1 (+bias2 if non-null)
// MODE 1: C = AB^T + addsrc (elementwise [M,N])
// MODE 2: C = relu(AB^T + bias1)
// MODE 3: C += rowscale[r*rs_stride] * (AB^T + bias1)
template<int MODE>
__global__ __launch_bounds__(256, 2)
void gemm128(const float* __restrict__ A, const float* __restrict__ W,
             float* __restrict__ C, int M, int N, int K,
             const float* __restrict__ bias1, const float* __restrict__ bias2,
             const float* __restrict__ addsrc,
             const float* __restrict__ rowscale, int rs_stride)
{
    __shared__ float As[2][8][128];
    __shared__ float Bs[2][8][128];

    const int tid = threadIdx.x;
    const int m0 = blockIdx.y << 7;
    const int n0 = blockIdx.x << 7;
    const int tx = tid & 15;       // 16 thread-cols
    const int ty = tid >> 4;       // 16 thread-rows
    const int lr = tid >> 1;       // load row 0..127
    const int lc = (tid & 1) << 2; // load col 0 or 4

    const float* Ap = A + (size_t)(m0 + lr) * K + lc;
    const float* Wp = W + (size_t)(n0 + lr) * K + lc;

    float acc[8][8];
    #pragma unroll
    for (int i = 0; i < 8; ++i)
        #pragma unroll
        for (int j = 0; j < 8; ++j) acc[i][j] = 0.f;

    // prologue: stage tile 0
    {
        float4 av = *(const float4*)Ap;
        float4 wv = *(const float4*)Wp;
        As[0][lc+0][lr] = av.x; As[0][lc+1][lr] = av.y;
        As[0][lc+2][lr] = av.z; As[0][lc+3][lr] = av.w;
        Bs[0][lc+0][lr] = wv.x; Bs[0][lc+1][lr] = wv.y;
        Bs[0][lc+2][lr] = wv.z; Bs[0][lc+3][lr] = wv.w;
    }
    __syncthreads();

    const int NT = K >> 3;
    for (int t = 0; t < NT; ++t) {
        const int buf = t & 1;
        float4 na, nw;
        if (t + 1 < NT) {
            na = *(const float4*)(Ap + ((t + 1) << 3));
            nw = *(const float4*)(Wp + ((t + 1) << 3));
        }
        #pragma unroll
        for (int kk = 0; kk < 8; ++kk) {
            float a[8], b[8];
            *(float4*)&a[0] = *(const float4*)&As[buf][kk][(ty << 3) + 0];
            *(float4*)&a[4] = *(const float4*)&As[buf][kk][(ty << 3) + 4];
            *(float4*)&b[0] = *(const float4*)&Bs[buf][kk][(tx << 3) + 0];
            *(float4*)&b[4] = *(const float4*)&Bs[buf][kk][(tx << 3) + 4];
            #pragma unroll
            for (int i = 0; i < 8; ++i)
                #pragma unroll
                for (int j = 0; j < 8; ++j)
                    acc[i][j] = fmaf(a[i], b[j], acc[i][j]);
        }
        if (t + 1 < NT) {
            const int nb = buf ^ 1;
            As[nb][lc+0][lr] = na.x; As[nb][lc+1][lr] = na.y;
            As[nb][lc+2][lr] = na.z; As[nb][lc+3][lr] = na.w;
            Bs[nb][lc+0][lr] = nw.x; Bs[nb][lc+1][lr] = nw.y;
            Bs[nb][lc+2][lr] = nw.z; Bs[nb][lc+3][lr] = nw.w;
        }
        __syncthreads();
    }

    const int r0 = m0 + (ty << 3);
    const int c0 = n0 + (tx << 3);

    float bb[8];
    if (MODE == 0 || MODE == 2 || MODE == 3) {
        #pragma unroll
        for (int j = 0; j < 8; ++j) {
            bb[j] = bias1[c0 + j];
            if (MODE == 0) { if (bias2) bb[j] += bias2[c0 + j]; }
        }
    }

    #pragma unroll
    for (int i = 0; i < 8; ++i) {
        const size_t off = (size_t)(r0 + i) * N + c0;
        float v[8];
        #pragma unroll
        for (int j = 0; j < 8; ++j) v[j] = acc[i][j];

        if (MODE == 0) {
            #pragma unroll
            for (int j = 0; j < 8; ++j) v[j] += bb[j];
        } else if (MODE == 1) {
            float4 s0 = *(const float4*)(addsrc + off);
            float4 s1 = *(const float4*)(addsrc + off + 4);
            v[0]+=s0.x; v[1]+=s0.y; v[2]+=s0.z; v[3]+=s0.w;
            v[4]+=s1.x; v[5]+=s1.y; v[6]+=s1.z; v[7]+=s1.w;
        } else if (MODE == 2) {
            #pragma unroll
            for (int j = 0; j < 8; ++j) v[j] = fmaxf(v[j] + bb[j], 0.f);
        } else if (MODE == 3) {
            const float sc = rowscale[(size_t)(r0 + i) * rs_stride];
            float4 cv0 = *(const float4*)(C + off);
            float4 cv1 = *(const float4*)(C + off + 4);
            v[0] = cv0.x + sc * (v[0] + bb[0]);
            v[1] = cv0.y + sc * (v[1] + bb[1]);
            v[2] = cv0.z + sc * (v[2] + bb[2]);
            v[3] = cv0.w + sc * (v[3] + bb[3]);
            v[4] = cv1.x + sc * (v[4] + bb[4]);
            v[5] = cv1.y + sc * (v[5] + bb[5]);
            v[6] = cv1.z + sc * (v[6] + bb[6]);
            v[7] = cv1.w + sc * (v[7] + bb[7]);
        }

        float4 o0 = make_float4(v[0], v[1], v[2], v[3]);
        float4 o1 = make_float4(v[4], v[5], v[6], v[7]);
        *(float4*)(C + off)     = o0;
        *(float4*)(C + off + 4) = o1;
    }
}

// ---------------- fused LSTM cell + halting update (one block per row) ----------
__global__ void lstm_cell(const float* __restrict__ gates,
                          const float* __restrict__ Whalt, const float* __restrict__ bhalt,
                          float* __restrict__ c, float* __restrict__ h,
                          float* __restrict__ hsum, float* __restrict__ hp,
                          float* __restrict__ rem)
{
    const int row = blockIdx.x;
    const int tid = threadIdx.x;               // 256 threads
    const float* gr = gates + (size_t)row * G4_;
    float part = 0.f;
    #pragma unroll
    for (int it = 0; it < H_ / 256; ++it) {
        const int idx = tid + it * 256;
        const float gi = gr[idx];
        const float gf = gr[H_ + idx];
        const float gg = gr[2 * H_ + idx];
        const float go = gr[3 * H_ + idx];
        const size_t o = (size_t)row * H_ + idx;
        float cv = c[o];
        cv = sigf(gf) * cv + sigf(gi) * tanhf(gg);
        const float hv = sigf(go) * tanhf(cv);
        c[o] = cv;
        h[o] = hv;
        hsum[o] += hv;
        part += hv * Whalt[idx];
    }
    __shared__ float red[256];
    red[tid] = part;
    __syncthreads();
    #pragma unroll
    for (int s = 128; s > 0; s >>= 1) {
        if (tid < s) red[tid] += red[tid + s];
        __syncthreads();
    }
    if (tid == 0) {
        const float y = sigf(red[0] + bhalt[0]);
        float hpv = hp[row];
        hpv = hpv + y * (1.f - hpv);
        hp[row] = hpv;
        rem[row] += 1.f - hpv;
    }
}

// ---------------- avg = rem * hsum / T ----------------
__global__ void avg_kernel(const float* __restrict__ hsum, const float* __restrict__ rem,
                           float* __restrict__ out)
{
    const size_t i = (size_t)blockIdx.x * blockDim.x + threadIdx.x;
    if (i < (size_t)B_ * H_) {
        out[i] = rem[i / H_] * hsum[i] / 10.0f;
    }
}

// ---------------- router: logits -> top2 -> softmax weights (zeros elsewhere) ---
__global__ void router(const float* __restrict__ x, const float* __restrict__ Wg,
                       const float* __restrict__ bg, float* __restrict__ w)
{
    const int row = blockIdx.x;
    const int tid = threadIdx.x;               // 128 threads
    const float* xr = x + (size_t)row * H_;
    float p0 = 0.f, p1 = 0.f, p2 = 0.f, p3 = 0.f;
    for (int k = tid; k < H_; k += 128) {
        const float xv = xr[k];
        p0 += xv * Wg[k];
        p1 += xv * Wg[H_ + k];
        p2 += xv * Wg[2 * H_ + k];
        p3 += xv * Wg[3 * H_ + k];
    }
    __shared__ float red[4][128];
    red[0][tid] = p0; red[1][tid] = p1; red[2][tid] = p2; red[3][tid] = p3;
    __syncthreads();
    #pragma unroll
    for (int s = 64; s > 0; s >>= 1) {
        if (tid < s) {
            #pragma unroll
            for (int e = 0; e < 4; ++e) red[e][tid] += red[e][tid + s];
        }
        __syncthreads();
    }
    if (tid == 0) {
        float lg[4];
        #pragma unroll
        for (int e = 0; e < 4; ++e) lg[e] = red[e][0] + bg[e];
        // top-2, ties -> lower index (matches jax.lax.top_k stability)
        int i1 = 0; float m1 = lg[0];
        #pragma unroll
        for (int e = 1; e < 4; ++e) if (lg[e] > m1) { m1 = lg[e]; i1 = e; }
        int i2 = -1; float m2 = -3.4e38f;
        #pragma unroll
        for (int e = 0; e < 4; ++e) if (e != i1 && lg[e] > m2) { m2 = lg[e]; i2 = e; }
        const float e2 = expf(m2 - m1);
        const float s  = 1.f + e2;
        float out4[4] = {0.f, 0.f, 0.f, 0.f};
        out4[i1] = 1.f / s;
        out4[i2] = e2 / s;
        #pragma unroll
        for (int e = 0; e < 4; ++e) w[row * 4 + e] = out4[e];
    }
}

// ---------------- final LayerNorm (one block per row) ----------------
__global__ void layernorm(const float* __restrict__ x, const float* __restrict__ gamma,
                          const float* __restrict__ beta, float* __restrict__ out)
{
    const int row = blockIdx.x;
    const int tid = threadIdx.x;               // 256 threads
    const float* xr = x + (size_t)row * D_;
    float v[D_ / 256];
    float s = 0.f;
    #pragma unroll
    for (int it = 0; it < D_ / 256; ++it) { v[it] = xr[tid + it * 256]; s += v[it]; }
    __shared__ float red[256];
    red[tid] = s;
    __syncthreads();
    #pragma unroll
    for (int st = 128; st > 0; st >>= 1) {
        if (tid < st) red[tid] += red[tid + st];
        __syncthreads();
    }
    const float mu = red[0] / (float)D_;
    __syncthreads();
    float s2 = 0.f;
    #pragma unroll
    for (int it = 0; it < D_ / 256; ++it) { const float d = v[it] - mu; s2 += d * d; }
    red[tid] = s2;
    __syncthreads();
    #pragma unroll
    for (int st = 128; st > 0; st >>= 1) {
        if (tid < st) red[tid] += red[tid + st];
        __syncthreads();
    }
    const float var = red[0] / (float)D_;
    const float inv = rsqrtf(var + 1e-5f);
    #pragma unroll
    for (int it = 0; it < D_ / 256; ++it) {
        const int cc = tid + it * 256;
        out[(size_t)row * D_ + cc] = (v[it] - mu) * inv * gamma[cc] + beta[cc];
    }
}

// ---------------- host ----------------
struct Ptrs {
    float *xWi, *gates, *h, *c, *hsum, *x0, *hmid, *accA, *accB, *hp, *rem, *w;
};

static Ptrs get_ptrs() {
    static Ptrs P = [] {
        Ptrs q{};
        cudaGetSymbolAddress((void**)&q.xWi,  g_xWi);
        cudaGetSymbolAddress((void**)&q.gates,g_gates);
        cudaGetSymbolAddress((void**)&q.h,    g_h);
        cudaGetSymbolAddress((void**)&q.c,    g_c);
        cudaGetSymbolAddress((void**)&q.hsum, g_hsum);
        cudaGetSymbolAddress((void**)&q.x0,   g_x0);
        cudaGetSymbolAddress((void**)&q.hmid, g_hmid);
        cudaGetSymbolAddress((void**)&q.accA, g_accA);
        cudaGetSymbolAddress((void**)&q.accB, g_accB);
        cudaGetSymbolAddress((void**)&q.hp,   g_hp);
        cudaGetSymbolAddress((void**)&q.rem,  g_rem);
        cudaGetSymbolAddress((void**)&q.w,    g_w);
        return q;
    }();
    return P;
}

extern "C" void kernel_launch(void* const* d_in, const int* in_sizes, int n_in,
                              void* d_out, int out_size)
{
    const float* x     = (const float*)d_in[0];
    const float* Wi    = (const float*)d_in[1];
    const float* Wh    = (const float*)d_in[2];
    const float* bi    = (const float*)d_in[3];
    const float* bh    = (const float*)d_in[4];
    const float* Whalt = (const float*)d_in[5];
    const float* bhalt = (const float*)d_in[6];
    const float* gateW = (const float*)d_in[7];
    const float* gateb = (const float*)d_in[8];
    const float* W1    = (const float*)d_in[9];
    const float* b1    = (const float*)d_in[10];
    const float* W2    = (const float*)d_in[11];
    const float* b2    = (const float*)d_in[12];
    const float* gamma = (const float*)d_in[13];
    const float* beta  = (const float*)d_in[14];
    float* out = (float*)d_out;

    Ptrs P = get_ptrs();

    // zero recurrent state
    fill0<<<2048, 256>>>(P.h,    (size_t)B_ * H_);
    fill0<<<2048, 256>>>(P.c,    (size_t)B_ * H_);
    fill0<<<2048, 256>>>(P.hsum, (size_t)B_ * H_);
    fill0<<<64,   256>>>(P.hp,   (size_t)B_);
    fill0<<<64,   256>>>(P.rem,  (size_t)B_);

    // xWi = x @ Wi^T + bi + bh   [B, 4H]
    dim3 gridG(G4_ / 128, B_ / 128);
    gemm128<0><<<gridG, 256>>>(x, Wi, P.xWi, B_, G4_, D_, bi, bh, nullptr, nullptr, 0);

    // T LSTM steps; at t=0 h==0 so gates == xWi (skip the GEMM entirely)
    for (int t = 0; t < T_; ++t) {
        const float* gptr;
        if (t == 0) {
            gptr = P.xWi;
        } else {
            gemm128<1><<<gridG, 256>>>(P.h, Wh, P.gates, B_, G4_, H_,
                                       nullptr, nullptr, P.xWi, nullptr, 0);
            gptr = P.gates;
        }
        lstm_cell<<<B_, 256>>>(gptr, Whalt, bhalt, P.c, P.h, P.hsum, P.hp, P.rem);
    }

    // avg = rem * hsum / T
    avg_kernel<<<(B_ * H_ + 255) / 256, 256>>>(P.hsum, P.rem, P.x0);

    // two MoE levels (dense compute, top-2 weights with zeros for unselected)
    dim3 gridH(H_ / 128, B_ / 128);
    const float* cur = P.x0;
    float* nxt = P.accA;
    for (int l = 0; l < L_; ++l) {
        router<<<B_, 128>>>(cur, gateW + (size_t)l * E_ * H_, gateb + (size_t)l * E_, P.w);
        fill0<<<2048, 256>>>(nxt, (size_t)B_ * D_);
        for (int e = 0; e < E_; ++e) {
            const size_t le = (size_t)l * E_ + e;
            const float* W1p = W1 + le * H_ * H_;
            const float* b1p = b1 + le * H_;
            const float* W2p = W2 + le * (size_t)D_ * H_;
            const float* b2p = b2 + le * D_;
            gemm128<2><<<gridH, 256>>>(cur, W1p, P.hmid, B_, H_, H_,
                                       b1p, nullptr, nullptr, nullptr, 0);
            gemm128<3><<<gridH, 256>>>(P.hmid, W2p, nxt, B_, D_, H_,
                                       b2p, nullptr, nullptr, P.w + e, E_);
        }
        cur = nxt;
        nxt = P.accB;
    }

    // final LayerNorm -> d_out
    layernorm<<<B_, 256>>>(cur, gamma, beta, out);
}